// round 2
// baseline (speedup 1.0000x reference)
#include <cuda_runtime.h>
#include <cuda_bf16.h>
#include <math.h>

#define BB 2
#define NN 1024
#define HH 128
#define WW 128
#define C0_SH 0.28209479177387814f
#define EXP_M10 4.5399929762484854e-05f

// ---------------- device scratch (no allocations allowed) ----------------
__device__ float4 g_prep[BB * NN * 3];      // unsorted packed gaussians
__device__ float  g_key[BB * NN];           // depth keys
__device__ float4 g_sorted[BB * NN * 3];    // sorted packed gaussians
__device__ float  g_rgb[BB * 3 * HH * WW];  // rendered rgb (clipped)
__device__ float  g_accum[4];               // l1rgb, ssim, l1depth, opac_reg sums

__constant__ float W7[7] = {
    0.03663284536919702f, 0.11128075847888776f, 0.21674532140370407f,
    0.27068466949642226f, 0.21674532140370407f, 0.11128075847888776f,
    0.03663284536919702f
};

// ---------------- zero accumulators ----------------
__global__ void zero_kernel() {
    if (threadIdx.x < 4) g_accum[threadIdx.x] = 0.0f;
}

// ---------------- preprocess: per-gaussian projection + conic + entropy ----------------
__global__ void preprocess_kernel(const float* __restrict__ gauss,
                                  const float* __restrict__ intr) {
    int gid = blockIdx.x * blockDim.x + threadIdx.x;
    float entropy = 0.0f;
    if (gid < BB * NN) {
        int b = gid / NN;
        const float* g = gauss + gid * 38;
        float m0 = g[0], m1 = g[1], m2 = g[2];
        float s0 = g[3], s1 = g[4], s2 = g[5];
        float qw = g[6], qx = g[7], qy = g[8], qz = g[9];
        float opac = g[10];
        float shr = g[11], shg = g[12], shb = g[13];

        float fx = intr[b * 9 + 0], cx = intr[b * 9 + 2];
        float fy = intr[b * 9 + 4], cy = intr[b * 9 + 5];

        float z  = fmaxf(m2, 1e-4f);
        float px = fx * m0 / z + cx;
        float py = fy * m1 / z + cy;

        // rotation matrix
        float R00 = 1.0f - 2.0f * (qy * qy + qz * qz);
        float R01 = 2.0f * (qx * qy - qw * qz);
        float R02 = 2.0f * (qx * qz + qw * qy);
        float R10 = 2.0f * (qx * qy + qw * qz);
        float R11 = 1.0f - 2.0f * (qx * qx + qz * qz);
        float R12 = 2.0f * (qy * qz - qw * qx);
        float R20 = 2.0f * (qx * qz - qw * qy);
        float R21 = 2.0f * (qy * qz + qw * qx);
        float R22 = 1.0f - 2.0f * (qx * qx + qy * qy);

        float v0 = s0 * s0, v1 = s1 * s1, v2 = s2 * s2;
        float M00 = R00 * R00 * v0 + R01 * R01 * v1 + R02 * R02 * v2;
        float M01 = R00 * R10 * v0 + R01 * R11 * v1 + R02 * R12 * v2;
        float M02 = R00 * R20 * v0 + R01 * R21 * v1 + R02 * R22 * v2;
        float M11 = R10 * R10 * v0 + R11 * R11 * v1 + R12 * R12 * v2;
        float M12 = R10 * R20 * v0 + R11 * R21 * v1 + R12 * R22 * v2;
        float M22 = R20 * R20 * v0 + R21 * R21 * v1 + R22 * R22 * v2;

        float zc  = fmaxf(m2, 1e-6f);
        float zsq = zc * zc;
        float a = fx / zc;
        float c = -fx * m0 / zsq;
        float bj = fy / zc;
        float d = -fy * m1 / zsq;

        float c00 = a * a * M00 + 2.0f * a * c * M02 + c * c * M22 + 0.3f;
        float c01 = a * bj * M01 + a * d * M02 + bj * c * M12 + c * d * M22;
        float c11 = bj * bj * M11 + 2.0f * bj * d * M12 + d * d * M22 + 0.3f;

        float det = fmaxf(c00 * c11 - c01 * c01, 1e-8f);
        float inv00 =  c11 / det;
        float inv11 =  c00 / det;
        float inv01 = -c01 / det;

        float h00 = -0.5f * inv00;
        float h01 = -inv01;
        float h11 = -0.5f * inv11;

        float cr = fminf(fmaxf(shr * C0_SH + 0.5f, 0.0f), 1.0f);
        float cg = fminf(fmaxf(shg * C0_SH + 0.5f, 0.0f), 1.0f);
        float cb = fminf(fmaxf(shb * C0_SH + 0.5f, 0.0f), 1.0f);

        g_prep[gid * 3 + 0] = make_float4(px, py, h00, h01);
        g_prep[gid * 3 + 1] = make_float4(h11, opac, cr, cg);
        g_prep[gid * 3 + 2] = make_float4(cb, z, 0.0f, 0.0f);
        g_key[gid] = z;

        float o = fminf(fmaxf(opac, 1e-6f), 1.0f - 1e-6f);
        entropy = -(o * logf(o) + (1.0f - o) * logf(1.0f - o));
    }
    // warp reduce + atomic
    for (int off = 16; off > 0; off >>= 1)
        entropy += __shfl_down_sync(0xffffffffu, entropy, off);
    if ((threadIdx.x & 31) == 0 && entropy != 0.0f)
        atomicAdd(&g_accum[3], entropy);
}

// ---------------- bitonic sort by depth + gather ----------------
__global__ void sort_kernel() {
    __shared__ float sk[NN];
    __shared__ int   si[NN];
    int b = blockIdx.x;
    int t = threadIdx.x;
    sk[t] = g_key[b * NN + t];
    si[t] = t;
    __syncthreads();
    for (int k = 2; k <= NN; k <<= 1) {
        for (int j = k >> 1; j > 0; j >>= 1) {
            int ixj = t ^ j;
            if (ixj > t) {
                bool up = ((t & k) == 0);
                float av = sk[t], bv = sk[ixj];
                if ((av > bv) == up) {
                    sk[t] = bv; sk[ixj] = av;
                    int tmp = si[t]; si[t] = si[ixj]; si[ixj] = tmp;
                }
            }
            __syncthreads();
        }
    }
    int s = si[t];
    int dst = (b * NN + t) * 3;
    int src = (b * NN + s) * 3;
    g_sorted[dst + 0] = g_prep[src + 0];
    g_sorted[dst + 1] = g_prep[src + 1];
    g_sorted[dst + 2] = g_prep[src + 2];
}

// ---------------- render + inline L1 reductions ----------------
#define TG 256  // gaussians per smem tile
__global__ __launch_bounds__(64) void render_kernel(const float* __restrict__ target_rgb,
                                                    const float* __restrict__ target_depth) {
    __shared__ float4 sg[TG * 3];
    int tx = threadIdx.x & 7;
    int ty = threadIdx.x >> 3;
    int x = blockIdx.x * 8 + tx;
    int y = blockIdx.y * 8 + ty;
    int b = blockIdx.z;
    float xf = (float)x, yf = (float)y;

    float accR = 0.0f, accG = 0.0f, accB = 0.0f, accD = 0.0f, T = 1.0f;

    const float4* src = g_sorted + b * NN * 3;
    for (int tile = 0; tile < NN / TG; tile++) {
        __syncthreads();
        for (int i = threadIdx.x; i < TG * 3; i += 64)
            sg[i] = src[tile * TG * 3 + i];
        __syncthreads();
#pragma unroll 4
        for (int i = 0; i < TG; i++) {
            float4 p0 = sg[i * 3 + 0];
            float4 p1 = sg[i * 3 + 1];
            float4 p2 = sg[i * 3 + 2];
            float dx = xf - p0.x;
            float dy = yf - p0.y;
            float power = (p0.z * dx + p0.w * dy) * dx + p1.x * dy * dy;
            float t = fminf(power, 0.0f);
            float e;
            if (t > -10.0f) e = __expf(t);
            else            e = EXP_M10;
            float alpha = fminf(e * p1.y, 0.99f);
            float w = T * alpha;
            accR += w * p1.z;
            accG += w * p1.w;
            accB += w * p2.x;
            accD += w * p2.y;
            T -= w;
        }
    }

    float r = fminf(fmaxf(accR, 0.0f), 1.0f);
    float g = fminf(fmaxf(accG, 0.0f), 1.0f);
    float bl = fminf(fmaxf(accB, 0.0f), 1.0f);

    int base = ((b * 3) * HH + y) * WW + x;
    g_rgb[base]                = r;
    g_rgb[base + HH * WW]      = g;
    g_rgb[base + 2 * HH * WW]  = bl;

    float tr = target_rgb[base];
    float tg = target_rgb[base + HH * WW];
    float tb = target_rgb[base + 2 * HH * WW];
    float l1 = fabsf(r - tr) + fabsf(g - tg) + fabsf(bl - tb);

    float td = target_depth[(b * HH + y) * WW + x];
    float dl = fabsf(accD - td);

    for (int off = 16; off > 0; off >>= 1) {
        l1 += __shfl_down_sync(0xffffffffu, l1, off);
        dl += __shfl_down_sync(0xffffffffu, dl, off);
    }
    if ((threadIdx.x & 31) == 0) {
        atomicAdd(&g_accum[0], l1);
        atomicAdd(&g_accum[2], dl);
    }
}

// ---------------- SSIM (direct 7x7, zero-padded SAME) ----------------
__global__ void ssim_kernel(const float* __restrict__ target_rgb) {
    int idx = blockIdx.x * blockDim.x + threadIdx.x;  // over B*3*H*W
    float val = 0.0f;
    if (idx < BB * 3 * HH * WW) {
        int x = idx & (WW - 1);
        int y = (idx >> 7) & (HH - 1);
        int bc = idx >> 14;  // b*3+c
        const float* im1 = g_rgb + bc * HH * WW;
        const float* im2 = target_rgb + bc * HH * WW;

        float S1 = 0.0f, S2 = 0.0f, S11 = 0.0f, S22 = 0.0f, S12 = 0.0f;
#pragma unroll
        for (int j = -3; j <= 3; j++) {
            int yy = y + j;
            if (yy < 0 || yy >= HH) continue;
            float wy = W7[j + 3];
#pragma unroll
            for (int i = -3; i <= 3; i++) {
                int xx = x + i;
                if (xx < 0 || xx >= WW) continue;
                float w = wy * W7[i + 3];
                float a = im1[yy * WW + xx];
                float bq = im2[yy * WW + xx];
                S1  += w * a;
                S2  += w * bq;
                S11 += w * a * a;
                S22 += w * bq * bq;
                S12 += w * a * bq;
            }
        }
        const float C1 = 1e-4f, C2 = 9e-4f;
        float mu1 = S1, mu2 = S2;
        float s1  = S11 - mu1 * mu1;
        float s2  = S22 - mu2 * mu2;
        float s12 = S12 - mu1 * mu2;
        val = ((2.0f * mu1 * mu2 + C1) * (2.0f * s12 + C2)) /
              ((mu1 * mu1 + mu2 * mu2 + C1) * (s1 + s2 + C2));
    }
    for (int off = 16; off > 0; off >>= 1)
        val += __shfl_down_sync(0xffffffffu, val, off);
    if ((threadIdx.x & 31) == 0)
        atomicAdd(&g_accum[1], val);
}

// ---------------- finalize ----------------
__global__ void finalize_kernel(float* out) {
    float l1rgb = g_accum[0] / (float)(BB * 3 * HH * WW);
    float ssim  = g_accum[1] / (float)(BB * 3 * HH * WW);
    float l1d   = g_accum[2] / (float)(BB * HH * WW);
    float opr   = g_accum[3] / (float)(BB * NN);
    out[0] = 0.8f * l1rgb + 0.2f * (1.0f - ssim) + 0.5f * l1d + 0.01f * opr;
}

extern "C" void kernel_launch(void* const* d_in, const int* in_sizes, int n_in,
                              void* d_out, int out_size) {
    const float* gauss        = (const float*)d_in[0];
    const float* intr         = (const float*)d_in[1];
    const float* target_rgb   = (const float*)d_in[2];
    const float* target_depth = (const float*)d_in[3];
    float* out = (float*)d_out;

    zero_kernel<<<1, 32>>>();
    preprocess_kernel<<<(BB * NN + 127) / 128, 128>>>(gauss, intr);
    sort_kernel<<<BB, NN>>>();
    render_kernel<<<dim3(WW / 8, HH / 8, BB), 64>>>(target_rgb, target_depth);
    ssim_kernel<<<(BB * 3 * HH * WW + 127) / 128, 128>>>(target_rgb);
    finalize_kernel<<<1, 1>>>(out);
}

// round 3
// speedup vs baseline: 1.1659x; 1.1659x over previous
#include <cuda_runtime.h>
#include <cuda_bf16.h>
#include <math.h>

#define BB 2
#define NN 1024
#define HH 128
#define WW 128
#define S_SEG 8
#define GSEG (NN / S_SEG)            // 128 gaussians per segment
#define NPX (HH * WW)                // 16384
#define C0_SH 0.28209479177387814f
#define EXP_M10 4.5399929762484854e-05f

// ---------------- device scratch ----------------
__device__ float4 g_prep[BB * NN * 3];
__device__ float4 g_sorted[BB * NN * 3];
__device__ float  g_pR[BB * S_SEG * NPX];
__device__ float  g_pG[BB * S_SEG * NPX];
__device__ float  g_pB[BB * S_SEG * NPX];
__device__ float  g_pD[BB * S_SEG * NPX];
__device__ float  g_pT[BB * S_SEG * NPX];
__device__ float  g_rgb[BB * 3 * NPX];
__device__ float  g_accum[4] = {0.f, 0.f, 0.f, 0.f};  // l1rgb, ssim, l1depth, opac

// ============ fused preprocess + bitonic sort (one block per batch) ============
__global__ __launch_bounds__(NN) void prep_sort_kernel(const float* __restrict__ gauss,
                                                       const float* __restrict__ intr) {
    __shared__ float sk[NN];
    __shared__ int   si[NN];
    int b = blockIdx.x;
    int t = threadIdx.x;
    int gid = b * NN + t;

    const float* g = gauss + gid * 38;
    float m0 = g[0], m1 = g[1], m2 = g[2];
    float s0 = g[3], s1 = g[4], s2 = g[5];
    float qw = g[6], qx = g[7], qy = g[8], qz = g[9];
    float opac = g[10];
    float shr = g[11], shg = g[12], shb = g[13];

    float fx = intr[b * 9 + 0], cx = intr[b * 9 + 2];
    float fy = intr[b * 9 + 4], cy = intr[b * 9 + 5];

    float z  = fmaxf(m2, 1e-4f);
    float px = fx * m0 / z + cx;
    float py = fy * m1 / z + cy;

    float R00 = 1.0f - 2.0f * (qy * qy + qz * qz);
    float R01 = 2.0f * (qx * qy - qw * qz);
    float R02 = 2.0f * (qx * qz + qw * qy);
    float R10 = 2.0f * (qx * qy + qw * qz);
    float R11 = 1.0f - 2.0f * (qx * qx + qz * qz);
    float R12 = 2.0f * (qy * qz - qw * qx);
    float R20 = 2.0f * (qx * qz - qw * qy);
    float R21 = 2.0f * (qy * qz + qw * qx);
    float R22 = 1.0f - 2.0f * (qx * qx + qy * qy);

    float v0 = s0 * s0, v1 = s1 * s1, v2 = s2 * s2;
    float M00 = R00 * R00 * v0 + R01 * R01 * v1 + R02 * R02 * v2;
    float M01 = R00 * R10 * v0 + R01 * R11 * v1 + R02 * R12 * v2;
    float M02 = R00 * R20 * v0 + R01 * R21 * v1 + R02 * R22 * v2;
    float M11 = R10 * R10 * v0 + R11 * R11 * v1 + R12 * R12 * v2;
    float M12 = R10 * R20 * v0 + R11 * R21 * v1 + R12 * R22 * v2;
    float M22 = R20 * R20 * v0 + R21 * R21 * v1 + R22 * R22 * v2;

    float zc  = fmaxf(m2, 1e-6f);
    float zsq = zc * zc;
    float a  = fx / zc;
    float c  = -fx * m0 / zsq;
    float bj = fy / zc;
    float d  = -fy * m1 / zsq;

    float c00 = a * a * M00 + 2.0f * a * c * M02 + c * c * M22 + 0.3f;
    float c01 = a * bj * M01 + a * d * M02 + bj * c * M12 + c * d * M22;
    float c11 = bj * bj * M11 + 2.0f * bj * d * M12 + d * d * M22 + 0.3f;

    float det = fmaxf(c00 * c11 - c01 * c01, 1e-8f);
    float inv00 =  c11 / det;
    float inv11 =  c00 / det;
    float inv01 = -c01 / det;

    float h00 = -0.5f * inv00;
    float h01 = -inv01;
    float h11 = -0.5f * inv11;

    float cr = fminf(fmaxf(shr * C0_SH + 0.5f, 0.0f), 1.0f);
    float cg = fminf(fmaxf(shg * C0_SH + 0.5f, 0.0f), 1.0f);
    float cb = fminf(fmaxf(shb * C0_SH + 0.5f, 0.0f), 1.0f);

    g_prep[gid * 3 + 0] = make_float4(px, py, h00, h01);
    g_prep[gid * 3 + 1] = make_float4(h11, opac, cr, cg);
    g_prep[gid * 3 + 2] = make_float4(cb, z, 0.0f, 0.0f);

    float o = fminf(fmaxf(opac, 1e-6f), 1.0f - 1e-6f);
    float entropy = -(o * logf(o) + (1.0f - o) * logf(1.0f - o));
    for (int off = 16; off > 0; off >>= 1)
        entropy += __shfl_down_sync(0xffffffffu, entropy, off);
    if ((t & 31) == 0) atomicAdd(&g_accum[3], entropy);

    // ---- bitonic sort (key = z) ----
    sk[t] = z;
    si[t] = t;
    __syncthreads();
    for (int k = 2; k <= NN; k <<= 1) {
        for (int j = k >> 1; j > 0; j >>= 1) {
            int ixj = t ^ j;
            if (ixj > t) {
                bool up = ((t & k) == 0);
                float av = sk[t], bv = sk[ixj];
                if ((av > bv) == up) {
                    sk[t] = bv; sk[ixj] = av;
                    int tmp = si[t]; si[t] = si[ixj]; si[ixj] = tmp;
                }
            }
            __syncthreads();
        }
    }
    int s   = si[t];
    int dst = (b * NN + t) * 3;
    int src = (b * NN + s) * 3;
    g_sorted[dst + 0] = g_prep[src + 0];
    g_sorted[dst + 1] = g_prep[src + 1];
    g_sorted[dst + 2] = g_prep[src + 2];
}

// ============ render: per-segment partial blend, 2 px / thread ============
__global__ __launch_bounds__(128) void render_kernel() {
    __shared__ float4 sg[GSEG * 3];
    int tile = blockIdx.x;           // 64 tiles of 16x16
    int seg  = blockIdx.y;
    int b    = blockIdx.z;
    int t    = threadIdx.x;

    int tile_x = (tile & 7) << 4;
    int tile_y = (tile >> 3) << 4;
    int x0 = tile_x + ((t & 7) << 1);
    int y  = tile_y + (t >> 3);
    float xf = (float)x0, yf = (float)y;

    const float4* src = g_sorted + (b * NN + seg * GSEG) * 3;
    for (int i = t; i < GSEG * 3; i += 128) sg[i] = src[i];
    __syncthreads();

    float aR0 = 0.f, aG0 = 0.f, aB0 = 0.f, aD0 = 0.f, T0 = 1.f;
    float aR1 = 0.f, aG1 = 0.f, aB1 = 0.f, aD1 = 0.f, T1 = 1.f;

#pragma unroll 2
    for (int i = 0; i < GSEG; i++) {
        float4 p0 = sg[i * 3 + 0];
        float4 p1 = sg[i * 3 + 1];
        float4 p2 = sg[i * 3 + 2];
        float dy  = yf - p0.y;
        float hdy = p0.w * dy;          // h01*dy
        float cyy = p1.x * dy * dy;     // h11*dy^2

        float dx0 = xf - p0.x;
        float pw0 = (p0.z * dx0 + hdy) * dx0 + cyy;
        float t0  = fminf(pw0, 0.0f);
        float e0  = (t0 > -10.0f) ? __expf(t0) : EXP_M10;
        float al0 = fminf(e0 * p1.y, 0.99f);
        float w0  = T0 * al0;
        aR0 += w0 * p1.z; aG0 += w0 * p1.w; aB0 += w0 * p2.x; aD0 += w0 * p2.y;
        T0  -= w0;

        float dx1 = dx0 + 1.0f;
        float pw1 = (p0.z * dx1 + hdy) * dx1 + cyy;
        float t1  = fminf(pw1, 0.0f);
        float e1  = (t1 > -10.0f) ? __expf(t1) : EXP_M10;
        float al1 = fminf(e1 * p1.y, 0.99f);
        float w1  = T1 * al1;
        aR1 += w1 * p1.z; aG1 += w1 * p1.w; aB1 += w1 * p2.x; aD1 += w1 * p2.y;
        T1  -= w1;
    }

    int px   = y * WW + x0;                       // even index
    int base = (b * S_SEG + seg) * NPX + px;
    *(float2*)&g_pR[base] = make_float2(aR0, aR1);
    *(float2*)&g_pG[base] = make_float2(aG0, aG1);
    *(float2*)&g_pB[base] = make_float2(aB0, aB1);
    *(float2*)&g_pD[base] = make_float2(aD0, aD1);
    *(float2*)&g_pT[base] = make_float2(T0, T1);
}

// ============ combine segments + L1 reductions ============
__global__ __launch_bounds__(256) void combine_kernel(const float* __restrict__ target_rgb,
                                                      const float* __restrict__ target_depth) {
    int idx = blockIdx.x * 256 + threadIdx.x;     // over B*NPX
    int b = idx >> 14;
    int p = idx & (NPX - 1);

    float aR = 0.f, aG = 0.f, aB = 0.f, aD = 0.f, T = 1.f;
#pragma unroll
    for (int s = 0; s < S_SEG; s++) {
        int o = (b * S_SEG + s) * NPX + p;
        aR += T * g_pR[o];
        aG += T * g_pG[o];
        aB += T * g_pB[o];
        aD += T * g_pD[o];
        T  *= g_pT[o];
    }

    float r  = fminf(fmaxf(aR, 0.0f), 1.0f);
    float g  = fminf(fmaxf(aG, 0.0f), 1.0f);
    float bl = fminf(fmaxf(aB, 0.0f), 1.0f);

    int base = (b * 3) * NPX + p;
    g_rgb[base]            = r;
    g_rgb[base + NPX]      = g;
    g_rgb[base + 2 * NPX]  = bl;

    float l1 = fabsf(r  - target_rgb[base]) +
               fabsf(g  - target_rgb[base + NPX]) +
               fabsf(bl - target_rgb[base + 2 * NPX]);
    float dl = fabsf(aD - target_depth[idx]);

    for (int off = 16; off > 0; off >>= 1) {
        l1 += __shfl_down_sync(0xffffffffu, l1, off);
        dl += __shfl_down_sync(0xffffffffu, dl, off);
    }
    if ((threadIdx.x & 31) == 0) {
        atomicAdd(&g_accum[0], l1);
        atomicAdd(&g_accum[2], dl);
    }
}

// ============ SSIM: smem halo tile, fully unrolled 7x7 ============
#define TSS 16
#define HALO 3
#define TP (TSS + 2 * HALO)   // 22
__global__ __launch_bounds__(256) void ssim_kernel(const float* __restrict__ target_rgb) {
    __shared__ float sA[TP * TP];
    __shared__ float sB[TP * TP];
    const float w7[7] = {0.03663284536919702f, 0.11128075847888776f, 0.21674532140370407f,
                         0.27068466949642226f, 0.21674532140370407f, 0.11128075847888776f,
                         0.03663284536919702f};

    int tile = blockIdx.x & 63;       // 8x8 tiles
    int bc   = blockIdx.x >> 6;       // b*3+c
    int tile_x = (tile & 7) << 4;
    int tile_y = (tile >> 3) << 4;
    int t = threadIdx.x;

    const float* im1 = g_rgb + bc * NPX;
    const float* im2 = target_rgb + bc * NPX;

    for (int i = t; i < TP * TP; i += 256) {
        int iy = i / TP, ix = i - iy * TP;
        int gy = tile_y - HALO + iy;
        int gx = tile_x - HALO + ix;
        bool ok = (gy >= 0) & (gy < HH) & (gx >= 0) & (gx < WW);
        sA[i] = ok ? im1[gy * WW + gx] : 0.0f;
        sB[i] = ok ? im2[gy * WW + gx] : 0.0f;
    }
    __syncthreads();

    int lx = t & 15, ly = t >> 4;
    int sbase = (ly + HALO) * TP + lx + HALO;

    float S1 = 0.f, S2 = 0.f, S11 = 0.f, S22 = 0.f, S12 = 0.f;
#pragma unroll
    for (int j = -3; j <= 3; j++) {
        float wy = w7[j + 3];
#pragma unroll
        for (int i = -3; i <= 3; i++) {
            float w = wy * w7[i + 3];
            float av = sA[sbase + j * TP + i];
            float bv = sB[sbase + j * TP + i];
            S1  += w * av;
            S2  += w * bv;
            S11 += w * av * av;
            S22 += w * bv * bv;
            S12 += w * av * bv;
        }
    }
    const float C1 = 1e-4f, C2 = 9e-4f;
    float s1  = S11 - S1 * S1;
    float s2  = S22 - S2 * S2;
    float s12 = S12 - S1 * S2;
    float val = ((2.0f * S1 * S2 + C1) * (2.0f * s12 + C2)) /
                ((S1 * S1 + S2 * S2 + C1) * (s1 + s2 + C2));

    for (int off = 16; off > 0; off >>= 1)
        val += __shfl_down_sync(0xffffffffu, val, off);
    if ((t & 31) == 0) atomicAdd(&g_accum[1], val);
}

// ============ finalize (and reset accumulators for next replay) ============
__global__ void finalize_kernel(float* out) {
    float l1rgb = g_accum[0] / (float)(BB * 3 * NPX);
    float ssim  = g_accum[1] / (float)(BB * 3 * NPX);
    float l1d   = g_accum[2] / (float)(BB * NPX);
    float opr   = g_accum[3] / (float)(BB * NN);
    out[0] = 0.8f * l1rgb + 0.2f * (1.0f - ssim) + 0.5f * l1d + 0.01f * opr;
    g_accum[0] = 0.f; g_accum[1] = 0.f; g_accum[2] = 0.f; g_accum[3] = 0.f;
}

extern "C" void kernel_launch(void* const* d_in, const int* in_sizes, int n_in,
                              void* d_out, int out_size) {
    const float* gauss        = (const float*)d_in[0];
    const float* intr         = (const float*)d_in[1];
    const float* target_rgb   = (const float*)d_in[2];
    const float* target_depth = (const float*)d_in[3];
    float* out = (float*)d_out;

    prep_sort_kernel<<<BB, NN>>>(gauss, intr);
    render_kernel<<<dim3(64, S_SEG, BB), 128>>>();
    combine_kernel<<<(BB * NPX) / 256, 256>>>(target_rgb, target_depth);
    ssim_kernel<<<64 * BB * 3, 256>>>(target_rgb);
    finalize_kernel<<<1, 1>>>(out);
}